// round 2
// baseline (speedup 1.0000x reference)
#include <cuda_runtime.h>
#include <math.h>

typedef unsigned long long u64;

__device__ __forceinline__ u64 pk2(float lo, float hi) {
    u64 r; asm("mov.b64 %0, {%1,%2};" : "=l"(r) : "f"(lo), "f"(hi)); return r;
}
__device__ __forceinline__ void upk2(u64 v, float& lo, float& hi) {
    asm("mov.b64 {%0,%1}, %2;" : "=f"(lo), "=f"(hi) : "l"(v));
}
__device__ __forceinline__ u64 ffma2(u64 a, u64 b, u64 c) {
    u64 d; asm("fma.rn.f32x2 %0, %1, %2, %3;" : "=l"(d) : "l"(a), "l"(b), "l"(c)); return d;
}

// ---------------- scratch (no allocations allowed -> __device__ globals) ---
__device__ float g_u1[32ull * 24 * 256 * 256];   // 201 MB
__device__ float g_s1[32ull * 27 * 256 * 256];   // 226 MB
__device__ float g_u2[32ull * 216 * 128 * 128];  // 453 MB

// ================== band-pass + modulus (stages 1 and 2) ===================
// group g uses phi[g%3], psi_{r,i}[(g%3)*8 + p]. 17 filters packed as 9
// f32x2 pairs (f17 dummy). Each thread: 4 output pixels (rows ty+8q), so the
// 9 w-pair broadcast loads amortize over 36 FFMA2 per tap.
#define TBX 32
#define TBY 32
#define BW  69            // 2*32+5 input cols
#define BH  69            // 2*32+5 input rows
#define EW  36            // padded even/odd half-tile width

__global__ __launch_bounds__(256) void band_kernel(
    const float* __restrict__ in,     // [B*G, HIN, WIN]
    const float* __restrict__ phi,    // [3, 49]
    const float* __restrict__ psi_r,  // [24, 49]
    const float* __restrict__ psi_i,  // [24, 49]
    float* __restrict__ phi_out,      // [B, PHI_C, HOUT, WOUT]
    float* __restrict__ mod_out,      // [B, G*8, HOUT, WOUT]
    int HIN, int WIN, int HOUT, int WOUT,
    int G, int PHI_C)
{
    __shared__ float te[BH * EW];     // even input columns
    __shared__ float to[BH * EW];     // odd input columns
    __shared__ __align__(16) float wsm[49 * 18];

    const int tid = threadIdx.x;
    const int bz  = blockIdx.z;
    const int b   = bz / G;
    const int g   = bz - b * G;
    const int ce  = g % 3;

    for (int i = tid; i < 49 * 18; i += 256) {
        int t = i / 18, f = i - t * 18;
        float w = 0.f;
        if (f == 0)       w = phi[ce * 49 + t];
        else if (f < 9)   w = psi_r[(ce * 8 + f - 1) * 49 + t];
        else if (f < 17)  w = psi_i[(ce * 8 + f - 9) * 49 + t];
        wsm[i] = w;
    }

    const int ox0 = blockIdx.x * TBX;
    const int oy0 = blockIdx.y * TBY;
    const int ix0 = ox0 * 2 - 3;
    const int iy0 = oy0 * 2 - 3;
    const float* inp = in + (size_t)bz * HIN * WIN;

    // prologue: incremental (r,c); 256 = 3*69 + 49
    {
        int r = tid / BW, c = tid - r * BW;
        for (int idx = tid; idx < BH * BW; idx += 256) {
            int iy = iy0 + r, ix = ix0 + c;
            float v = 0.f;
            if ((unsigned)iy < (unsigned)HIN && (unsigned)ix < (unsigned)WIN)
                v = inp[(size_t)iy * WIN + ix];
            if (c & 1) to[r * EW + (c >> 1)] = v;
            else       te[r * EW + (c >> 1)] = v;
            r += 3; c += 49; if (c >= BW) { c -= BW; r += 1; }
        }
    }
    __syncthreads();

    const int tx = tid & 31;
    const int ty = tid >> 5;          // pixels at output rows ty + 8q, q=0..3

    u64 acc[4][9];
    #pragma unroll
    for (int q = 0; q < 4; q++)
        #pragma unroll
        for (int j = 0; j < 9; j++) acc[q][j] = 0ull;

    #pragma unroll 1
    for (int ky = 0; ky < 7; ky++) {
        #pragma unroll
        for (int kx = 0; kx < 7; kx++) {
            const float* tt = (kx & 1) ? to : te;
            const int cc = tx + (kx >> 1);
            const u64* w2 = (const u64*)&wsm[(ky * 7 + kx) * 18];
            u64 w[9];
            #pragma unroll
            for (int j = 0; j < 9; j++) w[j] = w2[j];
            #pragma unroll
            for (int q = 0; q < 4; q++) {
                float v = tt[(2 * (ty + 8 * q) + ky) * EW + cc];
                u64 vv = pk2(v, v);
                #pragma unroll
                for (int j = 0; j < 9; j++) acc[q][j] = ffma2(vv, w[j], acc[q][j]);
            }
        }
    }

    const int HW = HOUT * WOUT;
    const int ox = ox0 + tx;
    #pragma unroll
    for (int q = 0; q < 4; q++) {
        float a[18];
        #pragma unroll
        for (int j = 0; j < 9; j++) upk2(acc[q][j], a[2 * j], a[2 * j + 1]);
        const int oy = oy0 + ty + 8 * q;
        phi_out[((size_t)b * PHI_C + g) * HW + oy * WOUT + ox] = a[0];
        float* mo = mod_out + ((size_t)(b * G + g) * 8) * HW + oy * WOUT + ox;
        #pragma unroll
        for (int p = 0; p < 8; p++)
            mo[(size_t)p * HW] = sqrtf(fmaf(a[1 + p], a[1 + p], a[9 + p] * a[9 + p]));
    }
}

// ============ depthwise stride-1 smoothing with phi[k%3], f32x2 ============
// Thread computes 8 rows x 2 columns (x, x+32) packed as f32x2. smem tile is
// pair-interleaved: sp[r][c] = (in[r][x0-3+c], in[r][x0-3+c+32]) so inner
// loads are single conflict-free LDS.64.
#define TSX 64
#define TSY 64
#define SW2 38            // pair columns (0..37)
#define SH2 70            // 64 + 6 halo rows

__global__ __launch_bounds__(256) void smooth_kernel(
    const float* __restrict__ in,   // [B*CIN, H, W]
    const float* __restrict__ phi,  // [3, 49]
    float* __restrict__ out,        // [B, OUTC, H, W]
    int H, int W, int CIN, int OUTC, int OUTOFF)
{
    __shared__ u64 sp[SH2 * SW2];
    __shared__ u64 wd[49];

    const int tid = threadIdx.x;
    const int bz  = blockIdx.z;
    const int b   = bz / CIN;
    const int k   = bz - b * CIN;
    const int ce  = k % 3;

    if (tid < 49) { float w = phi[ce * 49 + tid]; wd[tid] = pk2(w, w); }

    const int x0 = blockIdx.x * TSX;
    const int y0 = blockIdx.y * TSY;
    const float* inp = in + (size_t)bz * H * W;

    // prologue: incremental (r,c); 256 = 6*38 + 28
    {
        int r = tid / SW2, c = tid - r * SW2;
        for (int idx = tid; idx < SH2 * SW2; idx += 256) {
            int iy = y0 - 3 + r;
            int ixa = x0 - 3 + c;
            int ixb = ixa + 32;
            float va = 0.f, vb = 0.f;
            if ((unsigned)iy < (unsigned)H) {
                if ((unsigned)ixa < (unsigned)W) va = inp[(size_t)iy * W + ixa];
                if ((unsigned)ixb < (unsigned)W) vb = inp[(size_t)iy * W + ixb];
            }
            sp[idx] = pk2(va, vb);
            r += 6; c += 28; if (c >= SW2) { c -= SW2; r += 1; }
        }
    }
    __syncthreads();

    const int tx  = tid & 31;
    const int yc  = tid >> 5;
    const int ry0 = yc * 8;

    u64 acc[8];
    #pragma unroll
    for (int o = 0; o < 8; o++) acc[o] = 0ull;

    #pragma unroll 1
    for (int kx = 0; kx < 7; kx++) {
        u64 p[14];
        #pragma unroll
        for (int i = 0; i < 14; i++)
            p[i] = sp[(ry0 + i) * SW2 + tx + kx];
        #pragma unroll
        for (int ky = 0; ky < 7; ky++) {
            u64 w = wd[ky * 7 + kx];
            #pragma unroll
            for (int o = 0; o < 8; o++)
                acc[o] = ffma2(p[ky + o], w, acc[o]);
        }
    }

    float* po = out + ((size_t)b * OUTC + OUTOFF + k) * H * W;
    #pragma unroll
    for (int o = 0; o < 8; o++) {
        float a, bv; upk2(acc[o], a, bv);
        const int y = y0 + ry0 + o;
        po[(size_t)y * W + x0 + tx]      = a;
        po[(size_t)y * W + x0 + tx + 32] = bv;
    }
}

// ---------------- launcher -------------------------------------------------
extern "C" void kernel_launch(void* const* d_in, const int* in_sizes, int n_in,
                              void* d_out, int out_size)
{
    const float* x     = (const float*)d_in[0];
    const float* phi   = (const float*)d_in[1];
    const float* psi_r = (const float*)d_in[2];
    const float* psi_i = (const float*)d_in[3];
    float* out = (float*)d_out;

    float *u1, *s1, *u2;
    cudaGetSymbolAddress((void**)&u1, g_u1);
    cudaGetSymbolAddress((void**)&s1, g_s1);
    cudaGetSymbolAddress((void**)&u2, g_u2);

    // Stage 1: x [32,3,512,512] -> s0_phi into s1 ch 0-2, |U1| -> u1 [32,24,256,256]
    band_kernel<<<dim3(256 / TBX, 256 / TBY, 32 * 3), 256>>>(
        x, phi, psi_r, psi_i, s1, u1, 512, 512, 256, 256, 3, 27);

    // u1_smooth -> s1 ch 3-26
    smooth_kernel<<<dim3(256 / TSX, 256 / TSY, 32 * 24), 256>>>(
        u1, phi, s1, 256, 256, 24, 27, 3);

    // Stage 2: s1 [32,27,256,256] -> s1_phi into out ch 0-26, |U2| -> u2 [32,216,128,128]
    band_kernel<<<dim3(128 / TBX, 128 / TBY, 32 * 27), 256>>>(
        s1, phi, psi_r, psi_i, out, u2, 256, 256, 128, 128, 27, 243);

    // u2_smooth -> out ch 27-242
    smooth_kernel<<<dim3(128 / TSX, 128 / TSY, 32 * 216), 256>>>(
        u2, phi, out, 128, 128, 216, 243, 27);
}

// round 3
// speedup vs baseline: 1.7705x; 1.7705x over previous
#include <cuda_runtime.h>
#include <math.h>

typedef unsigned long long u64;

__device__ __forceinline__ u64 pk2(float lo, float hi) {
    u64 r; asm("mov.b64 %0, {%1,%2};" : "=l"(r) : "f"(lo), "f"(hi)); return r;
}
__device__ __forceinline__ void upk2(u64 v, float& lo, float& hi) {
    asm("mov.b64 {%0,%1}, %2;" : "=f"(lo), "=f"(hi) : "l"(v));
}
__device__ __forceinline__ u64 ffma2(u64 a, u64 b, u64 c) {
    u64 d; asm("fma.rn.f32x2 %0, %1, %2, %3;" : "=l"(d) : "l"(a), "l"(b), "l"(c)); return d;
}
__device__ __forceinline__ float sqrt_ap(float x) {
    float r; asm("sqrt.approx.f32 %0, %1;" : "=f"(r) : "f"(x)); return r;
}

// ---------------- scratch (no allocations allowed -> __device__ globals) ---
__device__ float g_u1[32ull * 24 * 256 * 256];   // 201 MB
__device__ float g_s1[32ull * 27 * 256 * 256];   // 226 MB
__device__ float g_u2[32ull * 216 * 128 * 128];  // 453 MB

// ================== band-pass + modulus (stages 1 and 2) ===================
// group g uses phi[g%3], psi_{r,i}[(g%3)*8+p]. 17 filters packed as 9 f32x2
// pairs (lane 17 dummy). 2 output pixels per thread (rows ty, ty+8) so the
// weight-pair loads amortize over 18 FFMA2 per tap. Weight rows padded to
// 20 floats (80B, 16B-aligned) so pairs load as 4xLDS.128 + 1xLDS.64.
#define TBX 32
#define TBY 16
#define BW  69            // 2*32+5 input cols
#define BH  37            // 2*16+5 input rows
#define EW  36            // even/odd half-tile padded width

__global__ __launch_bounds__(256, 4) void band_kernel(
    const float* __restrict__ in,     // [B*G, HIN, WIN]
    const float* __restrict__ phi,    // [3, 49]
    const float* __restrict__ psi_r,  // [24, 49]
    const float* __restrict__ psi_i,  // [24, 49]
    float* __restrict__ phi_out,      // [B, PHI_C, HOUT, WOUT]
    float* __restrict__ mod_out,      // [B, G*8, HOUT, WOUT]
    int HIN, int WIN, int HOUT, int WOUT,
    int G, int PHI_C)
{
    __shared__ float te[BH * EW];     // even input columns
    __shared__ float to[BH * EW];     // odd input columns
    __shared__ __align__(16) float wsm[49 * 20];

    const int tid = threadIdx.x;
    const int bz  = blockIdx.z;
    const int b   = bz / G;
    const int g   = bz - b * G;
    const int ce  = g % 3;

    for (int i = tid; i < 49 * 20; i += 256) {
        int t = i / 20, f = i - t * 20;
        float w = 0.f;
        if (f == 0)       w = phi[ce * 49 + t];
        else if (f < 9)   w = psi_r[(ce * 8 + f - 1) * 49 + t];
        else if (f < 17)  w = psi_i[(ce * 8 + f - 9) * 49 + t];
        wsm[i] = w;
    }

    const int ox0 = blockIdx.x * TBX;
    const int oy0 = blockIdx.y * TBY;
    const int ix0 = ox0 * 2 - 3;
    const int iy0 = oy0 * 2 - 3;
    const float* inp = in + (size_t)bz * HIN * WIN;

    // input tile -> even/odd split (zero-padded at borders)
    for (int idx = tid; idx < BH * BW; idx += 256) {
        int r = idx / BW, c = idx - r * BW;
        int iy = iy0 + r, ix = ix0 + c;
        float v = 0.f;
        if ((unsigned)iy < (unsigned)HIN && (unsigned)ix < (unsigned)WIN)
            v = inp[(size_t)iy * WIN + ix];
        if (c & 1) to[r * EW + (c >> 1)] = v;
        else       te[r * EW + (c >> 1)] = v;
    }
    __syncthreads();

    const int tx = tid & 31;
    const int ty = tid >> 5;          // output rows ty and ty+8

    u64 acc0[9], acc1[9];
    #pragma unroll
    for (int j = 0; j < 9; j++) { acc0[j] = 0ull; acc1[j] = 0ull; }

    const float* pe = te + 2 * ty * EW + tx;   // row offset for pixel 0
    const float* po = to + 2 * ty * EW + tx;

    #pragma unroll 1
    for (int ky = 0; ky < 7; ky++) {
        const int ro = ky * EW;
        #pragma unroll
        for (int kx = 0; kx < 7; kx++) {
            const float* t = (kx & 1) ? po : pe;
            const int cc = kx >> 1;
            const u64* w2 = (const u64*)(wsm + (ky * 7 + kx) * 20);
            float v0 = t[ro + cc];
            float v1 = t[ro + 16 * EW + cc];     // pixel row ty+8 -> input +16 rows
            u64 vv0 = pk2(v0, v0);
            u64 vv1 = pk2(v1, v1);
            #pragma unroll
            for (int j = 0; j < 9; j++) {
                u64 w = w2[j];
                acc0[j] = ffma2(vv0, w, acc0[j]);
                acc1[j] = ffma2(vv1, w, acc1[j]);
            }
        }
    }

    const int HW = HOUT * WOUT;
    const int ox = ox0 + tx;
    float a0[18], a1[18];
    #pragma unroll
    for (int j = 0; j < 9; j++) {
        upk2(acc0[j], a0[2 * j], a0[2 * j + 1]);
        upk2(acc1[j], a1[2 * j], a1[2 * j + 1]);
    }
    const int oyA = oy0 + ty, oyB = oy0 + ty + 8;
    float* pp = phi_out + ((size_t)b * PHI_C + g) * HW;
    pp[oyA * WOUT + ox] = a0[0];
    pp[oyB * WOUT + ox] = a1[0];
    float* mo = mod_out + ((size_t)(b * G + g) * 8) * HW + ox;
    #pragma unroll
    for (int p = 0; p < 8; p++) {
        mo[(size_t)p * HW + oyA * WOUT] = sqrt_ap(fmaf(a0[1 + p], a0[1 + p], a0[9 + p] * a0[9 + p]));
        mo[(size_t)p * HW + oyB * WOUT] = sqrt_ap(fmaf(a1[1 + p], a1[1 + p], a1[9 + p] * a1[9 + p]));
    }
}

// ============ depthwise stride-1 smoothing with phi[k%3], f32x2 ============
// Thread computes 8 rows x 2 cols (x, x+32) packed as f32x2. smem tile is
// pair-interleaved so inner loads are single conflict-free LDS.64. Row window
// loaded just-in-time inside the unrolled ky loop to limit live registers;
// launch_bounds(256,6) pins >= 6 CTAs/SM (48 warps).
#define TSX 64
#define TSY 64
#define SW2 38            // pair columns (0..37)
#define SH2 70            // 64 + 6 halo rows

__global__ __launch_bounds__(256, 6) void smooth_kernel(
    const float* __restrict__ in,   // [B*CIN, H, W]
    const float* __restrict__ phi,  // [3, 49]
    float* __restrict__ out,        // [B, OUTC, H, W]
    int H, int W, int CIN, int OUTC, int OUTOFF)
{
    __shared__ u64 sp[SH2 * SW2];
    __shared__ u64 wd[49];

    const int tid = threadIdx.x;
    const int bz  = blockIdx.z;
    const int b   = bz / CIN;
    const int k   = bz - b * CIN;
    const int ce  = k % 3;

    if (tid < 49) { float w = phi[ce * 49 + tid]; wd[tid] = pk2(w, w); }

    const int x0 = blockIdx.x * TSX;
    const int y0 = blockIdx.y * TSY;
    const float* inp = in + (size_t)bz * H * W;

    for (int idx = tid; idx < SH2 * SW2; idx += 256) {
        int r = idx / SW2, c = idx - r * SW2;
        int iy  = y0 - 3 + r;
        int ixa = x0 - 3 + c;
        int ixb = ixa + 32;
        float va = 0.f, vb = 0.f;
        if ((unsigned)iy < (unsigned)H) {
            if ((unsigned)ixa < (unsigned)W) va = inp[(size_t)iy * W + ixa];
            if ((unsigned)ixb < (unsigned)W) vb = inp[(size_t)iy * W + ixb];
        }
        sp[idx] = pk2(va, vb);
    }
    __syncthreads();

    const int tx  = tid & 31;
    const int yc  = tid >> 5;
    const int ry0 = yc * 8;

    u64 acc[8];
    #pragma unroll
    for (int o = 0; o < 8; o++) acc[o] = 0ull;

    const u64* base = sp + ry0 * SW2 + tx;

    #pragma unroll 1
    for (int kx = 0; kx < 7; kx++) {
        const u64* bp = base + kx;
        u64 pv[14];
        #pragma unroll
        for (int i = 0; i < 7; i++)
            pv[i] = bp[i * SW2];
        #pragma unroll
        for (int ky = 0; ky < 7; ky++) {
            pv[ky + 7] = bp[(ky + 7) * SW2];          // just-in-time window extend
            u64 w = wd[ky * 7 + kx];
            #pragma unroll
            for (int o = 0; o < 8; o++)
                acc[o] = ffma2(pv[ky + o], w, acc[o]);
        }
    }

    float* po = out + ((size_t)b * OUTC + OUTOFF + k) * H * W;
    #pragma unroll
    for (int o = 0; o < 8; o++) {
        float a, bv; upk2(acc[o], a, bv);
        const int y = y0 + ry0 + o;
        po[(size_t)y * W + x0 + tx]      = a;
        po[(size_t)y * W + x0 + tx + 32] = bv;
    }
}

// ---------------- launcher -------------------------------------------------
extern "C" void kernel_launch(void* const* d_in, const int* in_sizes, int n_in,
                              void* d_out, int out_size)
{
    const float* x     = (const float*)d_in[0];
    const float* phi   = (const float*)d_in[1];
    const float* psi_r = (const float*)d_in[2];
    const float* psi_i = (const float*)d_in[3];
    float* out = (float*)d_out;

    float *u1, *s1, *u2;
    cudaGetSymbolAddress((void**)&u1, g_u1);
    cudaGetSymbolAddress((void**)&s1, g_s1);
    cudaGetSymbolAddress((void**)&u2, g_u2);

    // Stage 1: x [32,3,512,512] -> s0_phi into s1 ch 0-2, |U1| -> u1 [32,24,256,256]
    band_kernel<<<dim3(256 / TBX, 256 / TBY, 32 * 3), 256>>>(
        x, phi, psi_r, psi_i, s1, u1, 512, 512, 256, 256, 3, 27);

    // u1_smooth -> s1 ch 3-26
    smooth_kernel<<<dim3(256 / TSX, 256 / TSY, 32 * 24), 256>>>(
        u1, phi, s1, 256, 256, 24, 27, 3);

    // Stage 2: s1 [32,27,256,256] -> s1_phi into out ch 0-26, |U2| -> u2 [32,216,128,128]
    band_kernel<<<dim3(128 / TBX, 128 / TBY, 32 * 27), 256>>>(
        s1, phi, psi_r, psi_i, out, u2, 256, 256, 128, 128, 27, 243);

    // u2_smooth -> out ch 27-242
    smooth_kernel<<<dim3(128 / TSX, 128 / TSY, 32 * 216), 256>>>(
        u2, phi, out, 128, 128, 216, 243, 27);
}

// round 4
// speedup vs baseline: 1.7792x; 1.0049x over previous
#include <cuda_runtime.h>
#include <math.h>

typedef unsigned long long u64;

__device__ __forceinline__ u64 pk2(float lo, float hi) {
    u64 r; asm("mov.b64 %0, {%1,%2};" : "=l"(r) : "f"(lo), "f"(hi)); return r;
}
__device__ __forceinline__ void upk2(u64 v, float& lo, float& hi) {
    asm("mov.b64 {%0,%1}, %2;" : "=f"(lo), "=f"(hi) : "l"(v));
}
__device__ __forceinline__ u64 ffma2(u64 a, u64 b, u64 c) {
    u64 d; asm("fma.rn.f32x2 %0, %1, %2, %3;" : "=l"(d) : "l"(a), "l"(b), "l"(c)); return d;
}
__device__ __forceinline__ float sqrt_ap(float x) {
    float r; asm("sqrt.approx.f32 %0, %1;" : "=f"(r) : "f"(x)); return r;
}

// ---------------- scratch (no allocations allowed -> __device__ globals) ---
__device__ float g_u1[32ull * 24 * 256 * 256];   // 201 MB
__device__ float g_s1[32ull * 27 * 256 * 256];   // 226 MB
__device__ float g_u2[32ull * 216 * 128 * 128];  // 453 MB

// ================== band-pass + modulus (stages 1 and 2) ===================
// group g uses phi[g%3], psi_{r,i}[(g%3)*8+p]. 17 filters as 9 f32x2 pairs
// (lane 17 dummy). 2 output pixels per thread (rows ty, ty+8). Weight rows
// padded to 20 floats (80B, 16B aligned) -> w pairs load as 4x LDS.128 + 1x
// LDS.64 (5 insts instead of 9).
#define TBX 32
#define TBY 16
#define BW  69            // 2*32+5 input cols
#define BH  37            // 2*16+5 input rows
#define EW  36            // even/odd half-tile padded width

__global__ __launch_bounds__(256, 4) void band_kernel(
    const float* __restrict__ in,     // [B*G, HIN, WIN]
    const float* __restrict__ phi,    // [3, 49]
    const float* __restrict__ psi_r,  // [24, 49]
    const float* __restrict__ psi_i,  // [24, 49]
    float* __restrict__ phi_out,      // [B, PHI_C, HOUT, WOUT]
    float* __restrict__ mod_out,      // [B, G*8, HOUT, WOUT]
    int HIN, int WIN, int HOUT, int WOUT,
    int G, int PHI_C)
{
    __shared__ __align__(16) float te[BH * EW];   // even input columns
    __shared__ __align__(16) float to[BH * EW];   // odd input columns
    __shared__ __align__(16) float wsm[49 * 20];

    const int tid = threadIdx.x;
    const int bz  = blockIdx.z;
    const int b   = bz / G;
    const int g   = bz - b * G;
    const int ce  = g % 3;

    for (int i = tid; i < 49 * 20; i += 256) {
        int t = i / 20, f = i - t * 20;
        float w = 0.f;
        if (f == 0)       w = phi[ce * 49 + t];
        else if (f < 9)   w = psi_r[(ce * 8 + f - 1) * 49 + t];
        else if (f < 17)  w = psi_i[(ce * 8 + f - 9) * 49 + t];
        wsm[i] = w;
    }

    const int ox0 = blockIdx.x * TBX;
    const int oy0 = blockIdx.y * TBY;
    const int ix0 = ox0 * 2 - 3;
    const int iy0 = oy0 * 2 - 3;
    const float* inp = in + (size_t)bz * HIN * WIN;

    // input tile -> even/odd split (zero-padded at borders)
    for (int idx = tid; idx < BH * BW; idx += 256) {
        int r = idx / BW, c = idx - r * BW;
        int iy = iy0 + r, ix = ix0 + c;
        float v = 0.f;
        if ((unsigned)iy < (unsigned)HIN && (unsigned)ix < (unsigned)WIN)
            v = inp[(size_t)iy * WIN + ix];
        if (c & 1) to[r * EW + (c >> 1)] = v;
        else       te[r * EW + (c >> 1)] = v;
    }
    __syncthreads();

    const int tx = tid & 31;
    const int ty = tid >> 5;          // output rows ty and ty+8

    u64 acc0[9], acc1[9];
    #pragma unroll
    for (int j = 0; j < 9; j++) { acc0[j] = 0ull; acc1[j] = 0ull; }

    const float* pe = te + 2 * ty * EW + tx;
    const float* po = to + 2 * ty * EW + tx;

    #pragma unroll 1
    for (int ky = 0; ky < 7; ky++) {
        const int ro = ky * EW;
        const float* wrow = wsm + ky * 7 * 20;
        #pragma unroll
        for (int kx = 0; kx < 7; kx++) {
            const float* t = (kx & 1) ? po : pe;
            const int cc = kx >> 1;
            float v0 = t[ro + cc];
            float v1 = t[ro + 16 * EW + cc];     // pixel row ty+8 -> +16 input rows
            u64 vv0 = pk2(v0, v0);
            u64 vv1 = pk2(v1, v1);

            const float* wr = wrow + kx * 20;
            // 9 weight pairs via 4x LDS.128 + 1x LDS.64 (wr is 16B aligned)
            u64 w[9];
            {
                const ulonglong2* wv = (const ulonglong2*)wr;
                ulonglong2 q0 = wv[0], q1 = wv[1], q2 = wv[2], q3 = wv[3];
                w[0] = q0.x; w[1] = q0.y; w[2] = q1.x; w[3] = q1.y;
                w[4] = q2.x; w[5] = q2.y; w[6] = q3.x; w[7] = q3.y;
                w[8] = *(const u64*)(wr + 16);
            }
            #pragma unroll
            for (int j = 0; j < 9; j++) {
                acc0[j] = ffma2(vv0, w[j], acc0[j]);
                acc1[j] = ffma2(vv1, w[j], acc1[j]);
            }
        }
    }

    const int HW = HOUT * WOUT;
    float a0[18], a1[18];
    #pragma unroll
    for (int j = 0; j < 9; j++) {
        upk2(acc0[j], a0[2 * j], a0[2 * j + 1]);
        upk2(acc1[j], a1[2 * j], a1[2 * j + 1]);
    }
    const int oyA = oy0 + ty;
    // precomputed base pointers (kill 64-bit IMAD chains in the epilogue)
    float* ppA = phi_out + ((size_t)b * PHI_C + g) * HW + oyA * WOUT + ox0 + tx;
    ppA[0]        = a0[0];
    ppA[8 * WOUT] = a1[0];
    float* moA = mod_out + ((size_t)(b * G + g) * 8) * HW + oyA * WOUT + ox0 + tx;
    #pragma unroll
    for (int p = 0; p < 8; p++) {
        moA[(size_t)p * HW]            = sqrt_ap(fmaf(a0[1 + p], a0[1 + p], a0[9 + p] * a0[9 + p]));
        moA[(size_t)p * HW + 8 * WOUT] = sqrt_ap(fmaf(a1[1 + p], a1[1 + p], a1[9 + p] * a1[9 + p]));
    }
}

// ============ depthwise stride-1 smoothing with phi[k%3], f32x2 ============
// Thread computes 8 rows x 2 cols (x, x+32) packed as f32x2. Pair-interleaved
// smem tile -> conflict-free LDS.64. Weights transposed to [kx][ky] (pad 8)
// so each kx's 7 pairs load as 3x LDS.128 + 1x LDS.64.
#define TSX 64
#define TSY 64
#define SW2 38            // pair columns
#define SH2 70            // 64 + 6 halo rows

__global__ __launch_bounds__(256, 6) void smooth_kernel(
    const float* __restrict__ in,   // [B*CIN, H, W]
    const float* __restrict__ phi,  // [3, 49]
    float* __restrict__ out,        // [B, OUTC, H, W]
    int H, int W, int CIN, int OUTC, int OUTOFF)
{
    __shared__ __align__(16) u64 sp[SH2 * SW2];
    __shared__ __align__(16) u64 wdt[7 * 8];     // [kx][ky], ky padded to 8

    const int tid = threadIdx.x;
    const int bz  = blockIdx.z;
    const int b   = bz / CIN;
    const int k   = bz - b * CIN;
    const int ce  = k % 3;

    if (tid < 56) {
        int kx = tid >> 3, ky = tid & 7;
        float w = (ky < 7) ? phi[ce * 49 + ky * 7 + kx] : 0.f;
        wdt[tid] = pk2(w, w);
    }

    const int x0 = blockIdx.x * TSX;
    const int y0 = blockIdx.y * TSY;
    const float* inp = in + (size_t)bz * H * W;

    for (int idx = tid; idx < SH2 * SW2; idx += 256) {
        int r = idx / SW2, c = idx - r * SW2;
        int iy  = y0 - 3 + r;
        int ixa = x0 - 3 + c;
        int ixb = ixa + 32;
        float va = 0.f, vb = 0.f;
        if ((unsigned)iy < (unsigned)H) {
            if ((unsigned)ixa < (unsigned)W) va = inp[(size_t)iy * W + ixa];
            if ((unsigned)ixb < (unsigned)W) vb = inp[(size_t)iy * W + ixb];
        }
        sp[idx] = pk2(va, vb);
    }
    __syncthreads();

    const int tx  = tid & 31;
    const int yc  = tid >> 5;
    const int ry0 = yc * 8;

    u64 acc[8];
    #pragma unroll
    for (int o = 0; o < 8; o++) acc[o] = 0ull;

    const u64* base = sp + ry0 * SW2 + tx;

    #pragma unroll 1
    for (int kx = 0; kx < 7; kx++) {
        const u64* bp = base + kx;
        // 7 weight pairs for this kx: 3x LDS.128 + 1x LDS.64 (broadcast)
        u64 w[7];
        {
            const ulonglong2* wv = (const ulonglong2*)(wdt + kx * 8);
            ulonglong2 q0 = wv[0], q1 = wv[1], q2 = wv[2];
            w[0] = q0.x; w[1] = q0.y; w[2] = q1.x; w[3] = q1.y;
            w[4] = q2.x; w[5] = q2.y;
            w[6] = *(const u64*)(wdt + kx * 8 + 6);
        }
        u64 pv[14];
        #pragma unroll
        for (int i = 0; i < 7; i++)
            pv[i] = bp[i * SW2];
        #pragma unroll
        for (int ky = 0; ky < 7; ky++) {
            pv[ky + 7] = bp[(ky + 7) * SW2];     // just-in-time window extend
            #pragma unroll
            for (int o = 0; o < 8; o++)
                acc[o] = ffma2(pv[ky + o], w[ky], acc[o]);
        }
    }

    float* po = out + ((size_t)b * OUTC + OUTOFF + k) * H * W
                    + (size_t)(y0 + ry0) * W + x0 + tx;
    #pragma unroll
    for (int o = 0; o < 8; o++) {
        float a, bv; upk2(acc[o], a, bv);
        po[(size_t)o * W]      = a;
        po[(size_t)o * W + 32] = bv;
    }
}

// ---------------- launcher -------------------------------------------------
extern "C" void kernel_launch(void* const* d_in, const int* in_sizes, int n_in,
                              void* d_out, int out_size)
{
    const float* x     = (const float*)d_in[0];
    const float* phi   = (const float*)d_in[1];
    const float* psi_r = (const float*)d_in[2];
    const float* psi_i = (const float*)d_in[3];
    float* out = (float*)d_out;

    float *u1, *s1, *u2;
    cudaGetSymbolAddress((void**)&u1, g_u1);
    cudaGetSymbolAddress((void**)&s1, g_s1);
    cudaGetSymbolAddress((void**)&u2, g_u2);

    // Stage 1: x [32,3,512,512] -> s0_phi into s1 ch 0-2, |U1| -> u1 [32,24,256,256]
    band_kernel<<<dim3(256 / TBX, 256 / TBY, 32 * 3), 256>>>(
        x, phi, psi_r, psi_i, s1, u1, 512, 512, 256, 256, 3, 27);

    // u1_smooth -> s1 ch 3-26
    smooth_kernel<<<dim3(256 / TSX, 256 / TSY, 32 * 24), 256>>>(
        u1, phi, s1, 256, 256, 24, 27, 3);

    // Stage 2: s1 [32,27,256,256] -> s1_phi into out ch 0-26, |U2| -> u2 [32,216,128,128]
    band_kernel<<<dim3(128 / TBX, 128 / TBY, 32 * 27), 256>>>(
        s1, phi, psi_r, psi_i, out, u2, 256, 256, 128, 128, 27, 243);

    // u2_smooth -> out ch 27-242
    smooth_kernel<<<dim3(128 / TSX, 128 / TSY, 32 * 216), 256>>>(
        u2, phi, out, 128, 128, 216, 243, 27);
}

// round 6
// speedup vs baseline: 1.8014x; 1.0125x over previous
#include <cuda_runtime.h>
#include <math.h>

typedef unsigned long long u64;

__device__ __forceinline__ u64 pk2(float lo, float hi) {
    u64 r; asm("mov.b64 %0, {%1,%2};" : "=l"(r) : "f"(lo), "f"(hi)); return r;
}
__device__ __forceinline__ void upk2(u64 v, float& lo, float& hi) {
    asm("mov.b64 {%0,%1}, %2;" : "=f"(lo), "=f"(hi) : "l"(v));
}
__device__ __forceinline__ u64 ffma2(u64 a, u64 b, u64 c) {
    u64 d; asm("fma.rn.f32x2 %0, %1, %2, %3;" : "=l"(d) : "l"(a), "l"(b), "l"(c)); return d;
}
__device__ __forceinline__ float sqrt_ap(float x) {
    float r; asm("sqrt.approx.f32 %0, %1;" : "=f"(r) : "f"(x)); return r;
}

// ---------------- scratch (no allocations allowed -> __device__ globals) ---
__device__ float g_u1[32ull * 24 * 256 * 256];   // 201 MB
__device__ float g_s1[32ull * 27 * 256 * 256];   // 226 MB
__device__ float g_u2[32ull * 216 * 128 * 128];  // 453 MB

// ================== band-pass + modulus (stages 1 and 2) ===================
// group g uses phi[g%3], psi_{r,i}[(g%3)*8+p]. 17 filters as 9 f32x2 pairs
// (lane 17 dummy). 2 output pixels per thread (rows ty, ty+8). Weight rows
// padded to 20 floats (80B, 16B aligned) -> w pairs load as 4x LDS.128 + 1x
// LDS.64.
#define TBX 32
#define TBY 16
#define BW  69            // 2*32+5 input cols
#define BH  37            // 2*16+5 input rows
#define EW  36            // even/odd half-tile padded width

__global__ __launch_bounds__(256, 4) void band_kernel(
    const float* __restrict__ in,     // [B*G, HIN, WIN]
    const float* __restrict__ phi,    // [3, 49]
    const float* __restrict__ psi_r,  // [24, 49]
    const float* __restrict__ psi_i,  // [24, 49]
    float* __restrict__ phi_out,      // [B, PHI_C, HOUT, WOUT]
    float* __restrict__ mod_out,      // [B, G*8, HOUT, WOUT]
    int HIN, int WIN, int HOUT, int WOUT,
    int G, int PHI_C)
{
    __shared__ __align__(16) float te[BH * EW];   // even input columns
    __shared__ __align__(16) float to[BH * EW];   // odd input columns
    __shared__ __align__(16) float wsm[49 * 20];

    const int tid = threadIdx.x;
    const int bz  = blockIdx.z;
    const int b   = bz / G;
    const int g   = bz - b * G;
    const int ce  = g % 3;

    for (int i = tid; i < 49 * 20; i += 256) {
        int t = i / 20, f = i - t * 20;
        float w = 0.f;
        if (f == 0)       w = phi[ce * 49 + t];
        else if (f < 9)   w = psi_r[(ce * 8 + f - 1) * 49 + t];
        else if (f < 17)  w = psi_i[(ce * 8 + f - 9) * 49 + t];
        wsm[i] = w;
    }

    const int ox0 = blockIdx.x * TBX;
    const int oy0 = blockIdx.y * TBY;
    const int ix0 = ox0 * 2 - 3;
    const int iy0 = oy0 * 2 - 3;
    const float* inp = in + (size_t)bz * HIN * WIN;

    // input tile -> even/odd split (zero-padded at borders)
    for (int idx = tid; idx < BH * BW; idx += 256) {
        int r = idx / BW, c = idx - r * BW;
        int iy = iy0 + r, ix = ix0 + c;
        float v = 0.f;
        if ((unsigned)iy < (unsigned)HIN && (unsigned)ix < (unsigned)WIN)
            v = inp[(size_t)iy * WIN + ix];
        if (c & 1) to[r * EW + (c >> 1)] = v;
        else       te[r * EW + (c >> 1)] = v;
    }
    __syncthreads();

    const int tx = tid & 31;
    const int ty = tid >> 5;          // output rows ty and ty+8

    u64 acc0[9], acc1[9];
    #pragma unroll
    for (int j = 0; j < 9; j++) { acc0[j] = 0ull; acc1[j] = 0ull; }

    const float* pe = te + 2 * ty * EW + tx;
    const float* po = to + 2 * ty * EW + tx;

    #pragma unroll 1
    for (int ky = 0; ky < 7; ky++) {
        const int ro = ky * EW;
        const float* wrow = wsm + ky * 7 * 20;
        #pragma unroll
        for (int kx = 0; kx < 7; kx++) {
            const float* t = (kx & 1) ? po : pe;
            const int cc = kx >> 1;
            float v0 = t[ro + cc];
            float v1 = t[ro + 16 * EW + cc];     // pixel row ty+8 -> +16 input rows
            u64 vv0 = pk2(v0, v0);
            u64 vv1 = pk2(v1, v1);

            const float* wr = wrow + kx * 20;
            u64 w[9];
            {
                const ulonglong2* wv = (const ulonglong2*)wr;
                ulonglong2 q0 = wv[0], q1 = wv[1], q2 = wv[2], q3 = wv[3];
                w[0] = q0.x; w[1] = q0.y; w[2] = q1.x; w[3] = q1.y;
                w[4] = q2.x; w[5] = q2.y; w[6] = q3.x; w[7] = q3.y;
                w[8] = *(const u64*)(wr + 16);
            }
            #pragma unroll
            for (int j = 0; j < 9; j++) {
                acc0[j] = ffma2(vv0, w[j], acc0[j]);
                acc1[j] = ffma2(vv1, w[j], acc1[j]);
            }
        }
    }

    const int HW = HOUT * WOUT;
    float a0[18], a1[18];
    #pragma unroll
    for (int j = 0; j < 9; j++) {
        upk2(acc0[j], a0[2 * j], a0[2 * j + 1]);
        upk2(acc1[j], a1[2 * j], a1[2 * j + 1]);
    }
    const int oyA = oy0 + ty;
    float* ppA = phi_out + ((size_t)b * PHI_C + g) * HW + oyA * WOUT + ox0 + tx;
    ppA[0]        = a0[0];
    ppA[8 * WOUT] = a1[0];
    float* moA = mod_out + ((size_t)(b * G + g) * 8) * HW + oyA * WOUT + ox0 + tx;
    #pragma unroll
    for (int p = 0; p < 8; p++) {
        moA[(size_t)p * HW]            = sqrt_ap(fmaf(a0[1 + p], a0[1 + p], a0[9 + p] * a0[9 + p]));
        moA[(size_t)p * HW + 8 * WOUT] = sqrt_ap(fmaf(a1[1 + p], a1[1 + p], a1[9 + p] * a1[9 + p]));
    }
}

// ============ depthwise stride-1 smoothing with phi[k%3], f32x2 ============
// Thread computes 8 rows x 2 cols (x, x+32) packed as f32x2. Pair-interleaved
// smem tile -> conflict-free LDS.64. Weights transposed [kx][ky] (pad 8).
// Rolling single-row scheme: each input row value is loaded once, fanned out
// to all valid accumulators (o = r - ky), then dead -> no load->use hazard on
// the same iteration, minimal live window.
#define TSX 64
#define TSY 64
#define SW2 38            // pair columns
#define SH2 70            // 64 + 6 halo rows

__global__ __launch_bounds__(256, 6) void smooth_kernel(
    const float* __restrict__ in,   // [B*CIN, H, W]
    const float* __restrict__ phi,  // [3, 49]
    float* __restrict__ out,        // [B, OUTC, H, W]
    int H, int W, int CIN, int OUTC, int OUTOFF)
{
    __shared__ __align__(16) u64 sp[SH2 * SW2];
    __shared__ __align__(16) u64 wdt[7 * 8];     // [kx][ky], ky padded to 8

    const int tid = threadIdx.x;
    const int bz  = blockIdx.z;
    const int b   = bz / CIN;
    const int k   = bz - b * CIN;
    const int ce  = k % 3;

    if (tid < 56) {
        int kx = tid >> 3, ky = tid & 7;
        float w = (ky < 7) ? phi[ce * 49 + ky * 7 + kx] : 0.f;
        wdt[tid] = pk2(w, w);
    }

    const int x0 = blockIdx.x * TSX;
    const int y0 = blockIdx.y * TSY;
    const float* inp = in + (size_t)bz * H * W;

    for (int idx = tid; idx < SH2 * SW2; idx += 256) {
        int r = idx / SW2, c = idx - r * SW2;
        int iy  = y0 - 3 + r;
        int ixa = x0 - 3 + c;
        int ixb = ixa + 32;
        float va = 0.f, vb = 0.f;
        if ((unsigned)iy < (unsigned)H) {
            if ((unsigned)ixa < (unsigned)W) va = inp[(size_t)iy * W + ixa];
            if ((unsigned)ixb < (unsigned)W) vb = inp[(size_t)iy * W + ixb];
        }
        sp[idx] = pk2(va, vb);
    }
    __syncthreads();

    const int tx  = tid & 31;
    const int yc  = tid >> 5;
    const int ry0 = yc * 8;

    u64 acc[8];
    #pragma unroll
    for (int o = 0; o < 8; o++) acc[o] = 0ull;

    const u64* base = sp + ry0 * SW2 + tx;

    #pragma unroll 1
    for (int kx = 0; kx < 7; kx++) {
        const u64* col = base + kx;
        // 7 weight pairs for this kx: 3x LDS.128 + 1x LDS.64 (broadcast)
        u64 w[7];
        {
            const ulonglong2* wv = (const ulonglong2*)(wdt + kx * 8);
            ulonglong2 q0 = wv[0], q1 = wv[1], q2 = wv[2];
            w[0] = q0.x; w[1] = q0.y; w[2] = q1.x; w[3] = q1.y;
            w[4] = q2.x; w[5] = q2.y;
            w[6] = *(const u64*)(wdt + kx * 8 + 6);
        }
        // rolling rows: row r feeds acc[r-ky] for valid ky; value dies after
        #pragma unroll
        for (int r = 0; r < 14; r++) {
            u64 v = col[r * SW2];
            #pragma unroll
            for (int ky = 0; ky < 7; ky++) {
                int o = r - ky;
                if (o >= 0 && o < 8)
                    acc[o] = ffma2(v, w[ky], acc[o]);
            }
        }
    }

    float* po = out + ((size_t)b * OUTC + OUTOFF + k) * H * W
                    + (size_t)(y0 + ry0) * W + x0 + tx;
    #pragma unroll
    for (int o = 0; o < 8; o++) {
        float a, bv; upk2(acc[o], a, bv);
        po[(size_t)o * W]      = a;
        po[(size_t)o * W + 32] = bv;
    }
}

// ---------------- launcher -------------------------------------------------
extern "C" void kernel_launch(void* const* d_in, const int* in_sizes, int n_in,
                              void* d_out, int out_size)
{
    const float* x     = (const float*)d_in[0];
    const float* phi   = (const float*)d_in[1];
    const float* psi_r = (const float*)d_in[2];
    const float* psi_i = (const float*)d_in[3];
    float* out = (float*)d_out;

    float *u1, *s1, *u2;
    cudaGetSymbolAddress((void**)&u1, g_u1);
    cudaGetSymbolAddress((void**)&s1, g_s1);
    cudaGetSymbolAddress((void**)&u2, g_u2);

    // Stage 1: x [32,3,512,512] -> s0_phi into s1 ch 0-2, |U1| -> u1 [32,24,256,256]
    band_kernel<<<dim3(256 / TBX, 256 / TBY, 32 * 3), 256>>>(
        x, phi, psi_r, psi_i, s1, u1, 512, 512, 256, 256, 3, 27);

    // u1_smooth -> s1 ch 3-26
    smooth_kernel<<<dim3(256 / TSX, 256 / TSY, 32 * 24), 256>>>(
        u1, phi, s1, 256, 256, 24, 27, 3);

    // Stage 2: s1 [32,27,256,256] -> s1_phi into out ch 0-26, |U2| -> u2 [32,216,128,128]
    band_kernel<<<dim3(128 / TBX, 128 / TBY, 32 * 27), 256>>>(
        s1, phi, psi_r, psi_i, out, u2, 256, 256, 128, 128, 27, 243);

    // u2_smooth -> out ch 27-242
    smooth_kernel<<<dim3(128 / TSX, 128 / TSY, 32 * 216), 256>>>(
        u2, phi, out, 128, 128, 216, 243, 27);
}

// round 7
// speedup vs baseline: 1.8025x; 1.0006x over previous
#include <cuda_runtime.h>
#include <math.h>

typedef unsigned long long u64;

__device__ __forceinline__ u64 pk2(float lo, float hi) {
    u64 r; asm("mov.b64 %0, {%1,%2};" : "=l"(r) : "f"(lo), "f"(hi)); return r;
}
__device__ __forceinline__ void upk2(u64 v, float& lo, float& hi) {
    asm("mov.b64 {%0,%1}, %2;" : "=f"(lo), "=f"(hi) : "l"(v));
}
__device__ __forceinline__ u64 ffma2(u64 a, u64 b, u64 c) {
    u64 d; asm("fma.rn.f32x2 %0, %1, %2, %3;" : "=l"(d) : "l"(a), "l"(b), "l"(c)); return d;
}
__device__ __forceinline__ float sqrt_ap(float x) {
    float r; asm("sqrt.approx.f32 %0, %1;" : "=f"(r) : "f"(x)); return r;
}

// ---------------- scratch (no allocations allowed -> __device__ globals) ---
__device__ float g_u1[32ull * 24 * 256 * 256];   // 201 MB
__device__ float g_s1[32ull * 27 * 256 * 256];   // 226 MB
__device__ float g_u2[32ull * 216 * 128 * 128];  // 453 MB

// ================== band-pass + modulus (stages 1 and 2) ===================
// group g uses phi[g%3], psi_{r,i}[(g%3)*8+p]. 17 filters as 9 f32x2 pairs
// (lane 17 dummy). 2 output pixels per thread (rows ty, ty+8). Weight rows
// padded to 20 floats (80B, 16B aligned) -> w pairs load as 4x LDS.128 + 1x
// LDS.64. All prologue loops use incremental (r,c) stepping - no int div.
#define TBX 32
#define TBY 16
#define BW  69            // 2*32+5 input cols
#define BH  37            // 2*16+5 input rows
#define EW  36            // even/odd half-tile padded width

__global__ __launch_bounds__(256, 4) void band_kernel(
    const float* __restrict__ in,     // [B*G, HIN, WIN]
    const float* __restrict__ phi,    // [3, 49]
    const float* __restrict__ psi_r,  // [24, 49]
    const float* __restrict__ psi_i,  // [24, 49]
    float* __restrict__ phi_out,      // [B, PHI_C, HOUT, WOUT]
    float* __restrict__ mod_out,      // [B, G*8, HOUT, WOUT]
    int HIN, int WIN, int HOUT, int WOUT,
    int G, int PHI_C)
{
    __shared__ __align__(16) float te[BH * EW];   // even input columns
    __shared__ __align__(16) float to[BH * EW];   // odd input columns
    __shared__ __align__(16) float wsm[49 * 20];

    const int tid = threadIdx.x;
    const int bz  = blockIdx.z;
    const int b   = bz / G;
    const int g   = bz - b * G;
    const int ce  = g % 3;

    // weight bank: incremental (t, f); 256 = 12*20 + 16
    {
        int t = tid / 20, f = tid - t * 20;          // one div at entry only
        for (int i = tid; i < 49 * 20; i += 256) {
            float w = 0.f;
            if (f == 0)       w = phi[ce * 49 + t];
            else if (f < 9)   w = psi_r[(ce * 8 + f - 1) * 49 + t];
            else if (f < 17)  w = psi_i[(ce * 8 + f - 9) * 49 + t];
            wsm[i] = w;
            t += 12; f += 16; if (f >= 20) { f -= 20; t += 1; }
        }
    }

    const int ox0 = blockIdx.x * TBX;
    const int oy0 = blockIdx.y * TBY;
    const int ix0 = ox0 * 2 - 3;
    const int iy0 = oy0 * 2 - 3;
    const float* inp = in + (size_t)bz * HIN * WIN;

    // input tile -> even/odd split; incremental (r,c); 256 = 3*69 + 49
    {
        int r = tid / BW, c = tid - r * BW;
        for (int idx = tid; idx < BH * BW; idx += 256) {
            int iy = iy0 + r, ix = ix0 + c;
            float v = 0.f;
            if ((unsigned)iy < (unsigned)HIN && (unsigned)ix < (unsigned)WIN)
                v = inp[(size_t)iy * WIN + ix];
            if (c & 1) to[r * EW + (c >> 1)] = v;
            else       te[r * EW + (c >> 1)] = v;
            r += 3; c += 49; if (c >= BW) { c -= BW; r += 1; }
        }
    }
    __syncthreads();

    const int tx = tid & 31;
    const int ty = tid >> 5;          // output rows ty and ty+8

    u64 acc0[9], acc1[9];
    #pragma unroll
    for (int j = 0; j < 9; j++) { acc0[j] = 0ull; acc1[j] = 0ull; }

    const float* pe = te + 2 * ty * EW + tx;
    const float* po = to + 2 * ty * EW + tx;

    #pragma unroll 1
    for (int ky = 0; ky < 7; ky++) {
        const int ro = ky * EW;
        const float* wrow = wsm + ky * 7 * 20;
        #pragma unroll
        for (int kx = 0; kx < 7; kx++) {
            const float* t = (kx & 1) ? po : pe;
            const int cc = kx >> 1;
            float v0 = t[ro + cc];
            float v1 = t[ro + 16 * EW + cc];     // pixel row ty+8 -> +16 input rows
            u64 vv0 = pk2(v0, v0);
            u64 vv1 = pk2(v1, v1);

            const float* wr = wrow + kx * 20;
            u64 w[9];
            {
                const ulonglong2* wv = (const ulonglong2*)wr;
                ulonglong2 q0 = wv[0], q1 = wv[1], q2 = wv[2], q3 = wv[3];
                w[0] = q0.x; w[1] = q0.y; w[2] = q1.x; w[3] = q1.y;
                w[4] = q2.x; w[5] = q2.y; w[6] = q3.x; w[7] = q3.y;
                w[8] = *(const u64*)(wr + 16);
            }
            #pragma unroll
            for (int j = 0; j < 9; j++) {
                acc0[j] = ffma2(vv0, w[j], acc0[j]);
                acc1[j] = ffma2(vv1, w[j], acc1[j]);
            }
        }
    }

    const int HW = HOUT * WOUT;
    float a0[18], a1[18];
    #pragma unroll
    for (int j = 0; j < 9; j++) {
        upk2(acc0[j], a0[2 * j], a0[2 * j + 1]);
        upk2(acc1[j], a1[2 * j], a1[2 * j + 1]);
    }
    const int oyA = oy0 + ty;
    float* ppA = phi_out + ((size_t)b * PHI_C + g) * HW + oyA * WOUT + ox0 + tx;
    ppA[0]        = a0[0];
    ppA[8 * WOUT] = a1[0];
    float* moA = mod_out + ((size_t)(b * G + g) * 8) * HW + oyA * WOUT + ox0 + tx;
    #pragma unroll
    for (int p = 0; p < 8; p++) {
        moA[(size_t)p * HW]            = sqrt_ap(fmaf(a0[1 + p], a0[1 + p], a0[9 + p] * a0[9 + p]));
        moA[(size_t)p * HW + 8 * WOUT] = sqrt_ap(fmaf(a1[1 + p], a1[1 + p], a1[9 + p] * a1[9 + p]));
    }
}

// ============ depthwise stride-1 smoothing with phi[k%3], f32x2 ============
// Thread computes 8 rows x 2 cols (x, x+32) packed as f32x2. Pair-interleaved
// smem tile -> conflict-free LDS.64. Weights transposed [kx][ky] (pad 8).
// Rolling single-row scheme. Prologue uses incremental (r,c) - no int div.
#define TSX 64
#define TSY 64
#define SW2 38            // pair columns
#define SH2 70            // 64 + 6 halo rows

__global__ __launch_bounds__(256, 6) void smooth_kernel(
    const float* __restrict__ in,   // [B*CIN, H, W]
    const float* __restrict__ phi,  // [3, 49]
    float* __restrict__ out,        // [B, OUTC, H, W]
    int H, int W, int CIN, int OUTC, int OUTOFF)
{
    __shared__ __align__(16) u64 sp[SH2 * SW2];
    __shared__ __align__(16) u64 wdt[7 * 8];     // [kx][ky], ky padded to 8

    const int tid = threadIdx.x;
    const int bz  = blockIdx.z;
    const int b   = bz / CIN;
    const int k   = bz - b * CIN;
    const int ce  = k % 3;

    if (tid < 56) {
        int kx = tid >> 3, ky = tid & 7;
        float w = (ky < 7) ? phi[ce * 49 + ky * 7 + kx] : 0.f;
        wdt[tid] = pk2(w, w);
    }

    const int x0 = blockIdx.x * TSX;
    const int y0 = blockIdx.y * TSY;
    const float* inp = in + (size_t)bz * H * W;

    // tile load: incremental (r,c); 256 = 6*38 + 28
    {
        int r = tid / SW2, c = tid - r * SW2;        // one div at entry only
        for (int idx = tid; idx < SH2 * SW2; idx += 256) {
            int iy  = y0 - 3 + r;
            int ixa = x0 - 3 + c;
            int ixb = ixa + 32;
            float va = 0.f, vb = 0.f;
            if ((unsigned)iy < (unsigned)H) {
                if ((unsigned)ixa < (unsigned)W) va = inp[(size_t)iy * W + ixa];
                if ((unsigned)ixb < (unsigned)W) vb = inp[(size_t)iy * W + ixb];
            }
            sp[idx] = pk2(va, vb);
            r += 6; c += 28; if (c >= SW2) { c -= SW2; r += 1; }
        }
    }
    __syncthreads();

    const int tx  = tid & 31;
    const int yc  = tid >> 5;
    const int ry0 = yc * 8;

    u64 acc[8];
    #pragma unroll
    for (int o = 0; o < 8; o++) acc[o] = 0ull;

    const u64* base = sp + ry0 * SW2 + tx;

    #pragma unroll 1
    for (int kx = 0; kx < 7; kx++) {
        const u64* col = base + kx;
        u64 w[7];
        {
            const ulonglong2* wv = (const ulonglong2*)(wdt + kx * 8);
            ulonglong2 q0 = wv[0], q1 = wv[1], q2 = wv[2];
            w[0] = q0.x; w[1] = q0.y; w[2] = q1.x; w[3] = q1.y;
            w[4] = q2.x; w[5] = q2.y;
            w[6] = *(const u64*)(wdt + kx * 8 + 6);
        }
        // rolling rows: row r feeds acc[r-ky] for valid ky; value dies after
        #pragma unroll
        for (int r = 0; r < 14; r++) {
            u64 v = col[r * SW2];
            #pragma unroll
            for (int ky = 0; ky < 7; ky++) {
                int o = r - ky;
                if (o >= 0 && o < 8)
                    acc[o] = ffma2(v, w[ky], acc[o]);
            }
        }
    }

    float* po = out + ((size_t)b * OUTC + OUTOFF + k) * H * W
                    + (size_t)(y0 + ry0) * W + x0 + tx;
    #pragma unroll
    for (int o = 0; o < 8; o++) {
        float a, bv; upk2(acc[o], a, bv);
        po[(size_t)o * W]      = a;
        po[(size_t)o * W + 32] = bv;
    }
}

// ---------------- launcher -------------------------------------------------
extern "C" void kernel_launch(void* const* d_in, const int* in_sizes, int n_in,
                              void* d_out, int out_size)
{
    const float* x     = (const float*)d_in[0];
    const float* phi   = (const float*)d_in[1];
    const float* psi_r = (const float*)d_in[2];
    const float* psi_i = (const float*)d_in[3];
    float* out = (float*)d_out;

    float *u1, *s1, *u2;
    cudaGetSymbolAddress((void**)&u1, g_u1);
    cudaGetSymbolAddress((void**)&s1, g_s1);
    cudaGetSymbolAddress((void**)&u2, g_u2);

    // Stage 1: x [32,3,512,512] -> s0_phi into s1 ch 0-2, |U1| -> u1 [32,24,256,256]
    band_kernel<<<dim3(256 / TBX, 256 / TBY, 32 * 3), 256>>>(
        x, phi, psi_r, psi_i, s1, u1, 512, 512, 256, 256, 3, 27);

    // u1_smooth -> s1 ch 3-26
    smooth_kernel<<<dim3(256 / TSX, 256 / TSY, 32 * 24), 256>>>(
        u1, phi, s1, 256, 256, 24, 27, 3);

    // Stage 2: s1 [32,27,256,256] -> s1_phi into out ch 0-26, |U2| -> u2 [32,216,128,128]
    band_kernel<<<dim3(128 / TBX, 128 / TBY, 32 * 27), 256>>>(
        s1, phi, psi_r, psi_i, out, u2, 256, 256, 128, 128, 27, 243);

    // u2_smooth -> out ch 27-242
    smooth_kernel<<<dim3(128 / TSX, 128 / TSY, 32 * 216), 256>>>(
        u2, phi, out, 128, 128, 216, 243, 27);
}

// round 9
// speedup vs baseline: 1.8265x; 1.0133x over previous
#include <cuda_runtime.h>
#include <math.h>

typedef unsigned long long u64;

__device__ __forceinline__ u64 pk2(float lo, float hi) {
    u64 r; asm("mov.b64 %0, {%1,%2};" : "=l"(r) : "f"(lo), "f"(hi)); return r;
}
__device__ __forceinline__ void upk2(u64 v, float& lo, float& hi) {
    asm("mov.b64 {%0,%1}, %2;" : "=f"(lo), "=f"(hi) : "l"(v));
}
// In-place accumulate: d is read-modify-write ("+l") so ptxas needs no
// register-pair copies around the asm (the "=l" form was generating ~2
// marshaling MOVs per FFMA2 -> the mystery alu=34%).
__device__ __forceinline__ void ffma2_acc(u64& c, u64 a, u64 b) {
    asm("fma.rn.f32x2 %0, %1, %2, %0;" : "+l"(c) : "l"(a), "l"(b));
}
__device__ __forceinline__ float sqrt_ap(float x) {
    float r; asm("sqrt.approx.f32 %0, %1;" : "=f"(r) : "f"(x)); return r;
}

// ---------------- scratch (no allocations allowed -> __device__ globals) ---
__device__ float g_u1[32ull * 24 * 256 * 256];   // 201 MB
__device__ float g_s1[32ull * 27 * 256 * 256];   // 226 MB
__device__ float g_u2[32ull * 216 * 128 * 128];  // 453 MB

// ================== band-pass + modulus (stages 1 and 2) ===================
#define TBX 32
#define TBY 16
#define BW  69            // 2*32+5 input cols
#define BH  37            // 2*16+5 input rows
#define EW  36            // even/odd half-tile padded width

__global__ __launch_bounds__(256, 4) void band_kernel(
    const float* __restrict__ in,     // [B*G, HIN, WIN]
    const float* __restrict__ phi,    // [3, 49]
    const float* __restrict__ psi_r,  // [24, 49]
    const float* __restrict__ psi_i,  // [24, 49]
    float* __restrict__ phi_out,      // [B, PHI_C, HOUT, WOUT]
    float* __restrict__ mod_out,      // [B, G*8, HOUT, WOUT]
    int HIN, int WIN, int HOUT, int WOUT,
    int G, int PHI_C)
{
    __shared__ __align__(16) float te[BH * EW];   // even input columns
    __shared__ __align__(16) float to[BH * EW];   // odd input columns
    __shared__ __align__(16) float wsm[49 * 20];

    const int tid = threadIdx.x;
    const int bz  = blockIdx.z;
    const int b   = bz / G;
    const int g   = bz - b * G;
    const int ce  = g % 3;

    // weight bank: incremental (t, f); 256 = 12*20 + 16
    {
        int t = tid / 20, f = tid - t * 20;
        for (int i = tid; i < 49 * 20; i += 256) {
            float w = 0.f;
            if (f == 0)       w = phi[ce * 49 + t];
            else if (f < 9)   w = psi_r[(ce * 8 + f - 1) * 49 + t];
            else if (f < 17)  w = psi_i[(ce * 8 + f - 9) * 49 + t];
            wsm[i] = w;
            t += 12; f += 16; if (f >= 20) { f -= 20; t += 1; }
        }
    }

    const int ox0 = blockIdx.x * TBX;
    const int oy0 = blockIdx.y * TBY;
    const int ix0 = ox0 * 2 - 3;
    const int iy0 = oy0 * 2 - 3;
    const float* inp = in + (size_t)bz * HIN * WIN;

    // input tile -> even/odd split; incremental (r,c); 256 = 3*69 + 49
    {
        int r = tid / BW, c = tid - r * BW;
        for (int idx = tid; idx < BH * BW; idx += 256) {
            int iy = iy0 + r, ix = ix0 + c;
            float v = 0.f;
            if ((unsigned)iy < (unsigned)HIN && (unsigned)ix < (unsigned)WIN)
                v = inp[(size_t)iy * WIN + ix];
            if (c & 1) to[r * EW + (c >> 1)] = v;
            else       te[r * EW + (c >> 1)] = v;
            r += 3; c += 49; if (c >= BW) { c -= BW; r += 1; }
        }
    }
    __syncthreads();

    const int tx = tid & 31;
    const int ty = tid >> 5;          // output rows ty and ty+8

    u64 acc0[9], acc1[9];
    #pragma unroll
    for (int j = 0; j < 9; j++) { acc0[j] = 0ull; acc1[j] = 0ull; }

    const float* pe = te + 2 * ty * EW + tx;
    const float* po = to + 2 * ty * EW + tx;

    #pragma unroll 1
    for (int ky = 0; ky < 7; ky++) {
        const int ro = ky * EW;
        const float* wrow = wsm + ky * 7 * 20;
        #pragma unroll
        for (int kx = 0; kx < 7; kx++) {
            const float* t = (kx & 1) ? po : pe;
            const int cc = kx >> 1;
            float v0 = t[ro + cc];
            float v1 = t[ro + 16 * EW + cc];     // pixel row ty+8 -> +16 input rows
            u64 vv0 = pk2(v0, v0);
            u64 vv1 = pk2(v1, v1);

            const float* wr = wrow + kx * 20;
            u64 w[9];
            {
                const ulonglong2* wv = (const ulonglong2*)wr;
                ulonglong2 q0 = wv[0], q1 = wv[1], q2 = wv[2], q3 = wv[3];
                w[0] = q0.x; w[1] = q0.y; w[2] = q1.x; w[3] = q1.y;
                w[4] = q2.x; w[5] = q2.y; w[6] = q3.x; w[7] = q3.y;
                w[8] = *(const u64*)(wr + 16);
            }
            #pragma unroll
            for (int j = 0; j < 9; j++) {
                ffma2_acc(acc0[j], vv0, w[j]);
                ffma2_acc(acc1[j], vv1, w[j]);
            }
        }
    }

    const int HW = HOUT * WOUT;
    float a0[18], a1[18];
    #pragma unroll
    for (int j = 0; j < 9; j++) {
        upk2(acc0[j], a0[2 * j], a0[2 * j + 1]);
        upk2(acc1[j], a1[2 * j], a1[2 * j + 1]);
    }
    const int oyA = oy0 + ty;
    float* ppA = phi_out + ((size_t)b * PHI_C + g) * HW + oyA * WOUT + ox0 + tx;
    ppA[0]        = a0[0];
    ppA[8 * WOUT] = a1[0];
    float* moA = mod_out + ((size_t)(b * G + g) * 8) * HW + oyA * WOUT + ox0 + tx;
    #pragma unroll
    for (int p = 0; p < 8; p++) {
        moA[(size_t)p * HW]            = sqrt_ap(fmaf(a0[1 + p], a0[1 + p], a0[9 + p] * a0[9 + p]));
        moA[(size_t)p * HW + 8 * WOUT] = sqrt_ap(fmaf(a1[1 + p], a1[1 + p], a1[9 + p] * a1[9 + p]));
    }
}

// ============ depthwise stride-1 smoothing with phi[k%3], f32x2 ============
#define TSX 64
#define TSY 64
#define SW2 38            // pair columns
#define SH2 70            // 64 + 6 halo rows

__global__ __launch_bounds__(256, 6) void smooth_kernel(
    const float* __restrict__ in,   // [B*CIN, H, W]
    const float* __restrict__ phi,  // [3, 49]
    float* __restrict__ out,        // [B, OUTC, H, W]
    int H, int W, int CIN, int OUTC, int OUTOFF)
{
    __shared__ __align__(16) u64 sp[SH2 * SW2];
    __shared__ __align__(16) u64 wdt[7 * 8];     // [kx][ky], ky padded to 8

    const int tid = threadIdx.x;
    const int bz  = blockIdx.z;
    const int b   = bz / CIN;
    const int k   = bz - b * CIN;
    const int ce  = k % 3;

    if (tid < 56) {
        int kx = tid >> 3, ky = tid & 7;
        float w = (ky < 7) ? phi[ce * 49 + ky * 7 + kx] : 0.f;
        wdt[tid] = pk2(w, w);
    }

    const int x0 = blockIdx.x * TSX;
    const int y0 = blockIdx.y * TSY;
    const float* inp = in + (size_t)bz * H * W;

    // tile load: incremental (r,c); 256 = 6*38 + 28
    {
        int r = tid / SW2, c = tid - r * SW2;
        for (int idx = tid; idx < SH2 * SW2; idx += 256) {
            int iy  = y0 - 3 + r;
            int ixa = x0 - 3 + c;
            int ixb = ixa + 32;
            float va = 0.f, vb = 0.f;
            if ((unsigned)iy < (unsigned)H) {
                if ((unsigned)ixa < (unsigned)W) va = inp[(size_t)iy * W + ixa];
                if ((unsigned)ixb < (unsigned)W) vb = inp[(size_t)iy * W + ixb];
            }
            sp[idx] = pk2(va, vb);
            r += 6; c += 28; if (c >= SW2) { c -= SW2; r += 1; }
        }
    }
    __syncthreads();

    const int tx  = tid & 31;
    const int yc  = tid >> 5;
    const int ry0 = yc * 8;

    u64 acc[8];
    #pragma unroll
    for (int o = 0; o < 8; o++) acc[o] = 0ull;

    const u64* base = sp + ry0 * SW2 + tx;

    #pragma unroll 1
    for (int kx = 0; kx < 7; kx++) {
        const u64* col = base + kx;
        u64 w[7];
        {
            const ulonglong2* wv = (const ulonglong2*)(wdt + kx * 8);
            ulonglong2 q0 = wv[0], q1 = wv[1], q2 = wv[2];
            w[0] = q0.x; w[1] = q0.y; w[2] = q1.x; w[3] = q1.y;
            w[4] = q2.x; w[5] = q2.y;
            w[6] = *(const u64*)(wdt + kx * 8 + 6);
        }
        // rolling rows: row r feeds acc[r-ky] for valid ky; value dies after
        #pragma unroll
        for (int r = 0; r < 14; r++) {
            u64 v = col[r * SW2];
            #pragma unroll
            for (int ky = 0; ky < 7; ky++) {
                int o = r - ky;
                if (o >= 0 && o < 8)
                    ffma2_acc(acc[o], v, w[ky]);
            }
        }
    }

    float* po = out + ((size_t)b * OUTC + OUTOFF + k) * H * W
                    + (size_t)(y0 + ry0) * W + x0 + tx;
    #pragma unroll
    for (int o = 0; o < 8; o++) {
        float a, bv; upk2(acc[o], a, bv);
        po[(size_t)o * W]      = a;
        po[(size_t)o * W + 32] = bv;
    }
}

// ---------------- launcher -------------------------------------------------
extern "C" void kernel_launch(void* const* d_in, const int* in_sizes, int n_in,
                              void* d_out, int out_size)
{
    const float* x     = (const float*)d_in[0];
    const float* phi   = (const float*)d_in[1];
    const float* psi_r = (const float*)d_in[2];
    const float* psi_i = (const float*)d_in[3];
    float* out = (float*)d_out;

    float *u1, *s1, *u2;
    cudaGetSymbolAddress((void**)&u1, g_u1);
    cudaGetSymbolAddress((void**)&s1, g_s1);
    cudaGetSymbolAddress((void**)&u2, g_u2);

    // Stage 1: x [32,3,512,512] -> s0_phi into s1 ch 0-2, |U1| -> u1 [32,24,256,256]
    band_kernel<<<dim3(256 / TBX, 256 / TBY, 32 * 3), 256>>>(
        x, phi, psi_r, psi_i, s1, u1, 512, 512, 256, 256, 3, 27);

    // u1_smooth -> s1 ch 3-26
    smooth_kernel<<<dim3(256 / TSX, 256 / TSY, 32 * 24), 256>>>(
        u1, phi, s1, 256, 256, 24, 27, 3);

    // Stage 2: s1 [32,27,256,256] -> s1_phi into out ch 0-26, |U2| -> u2 [32,216,128,128]
    band_kernel<<<dim3(128 / TBX, 128 / TBY, 32 * 27), 256>>>(
        s1, phi, psi_r, psi_i, out, u2, 256, 256, 128, 128, 27, 243);

    // u2_smooth -> out ch 27-242
    smooth_kernel<<<dim3(128 / TSX, 128 / TSY, 32 * 216), 256>>>(
        u2, phi, out, 128, 128, 216, 243, 27);
}